// round 1
// baseline (speedup 1.0000x reference)
#include <cuda_runtime.h>

#define B_ 4
#define T_ 4096
#define C_ 1024
#define H_ 64

// scratch for q,k,v : [B,T,H] each (4 MB each, static device arrays)
__device__ float g_q[B_*T_*H_];
__device__ float g_k[B_*T_*H_];
__device__ float g_v[B_*T_*H_];

// ---------------------------------------------------------------------------
// Kernel 1: QKV projection GEMM. Y = X @ W, X:[B*T, C], W:[C, H].
// grid = (B*T/64, 3), block = 256 threads (16x16), 4x4 register microtile.
// ---------------------------------------------------------------------------
__global__ __launch_bounds__(256) void qkv_kernel(
    const float* __restrict__ x,
    const float* __restrict__ Wk,
    const float* __restrict__ Wq,
    const float* __restrict__ Wv)
{
    __shared__ float Xs[64][33];   // +1 pad: conflict-free column reads
    __shared__ float Ws[32][64];

    const float* W;
    float* out;
    if (blockIdx.y == 0)      { W = Wk; out = g_k; }
    else if (blockIdx.y == 1) { W = Wq; out = g_q; }
    else                      { W = Wv; out = g_v; }

    const int row0 = blockIdx.x * 64;
    const int tid  = threadIdx.x;
    const int tx   = tid & 15;
    const int ty   = tid >> 4;

    float acc[4][4] = {};

    for (int k0 = 0; k0 < C_; k0 += 32) {
        #pragma unroll
        for (int i = tid; i < 64*32; i += 256) {
            int r = i >> 5, c = i & 31;
            Xs[r][c] = x[(size_t)(row0 + r) * C_ + k0 + c];
        }
        #pragma unroll
        for (int i = tid; i < 32*64; i += 256) {
            int r = i >> 6, c = i & 63;
            Ws[r][c] = W[(size_t)(k0 + r) * H_ + c];
        }
        __syncthreads();

        #pragma unroll
        for (int kk = 0; kk < 32; kk++) {
            float a[4];
            #pragma unroll
            for (int i = 0; i < 4; i++) a[i] = Xs[ty*4 + i][kk];
            float4 b4 = *reinterpret_cast<const float4*>(&Ws[kk][tx*4]);
            acc[0][0] += a[0]*b4.x; acc[0][1] += a[0]*b4.y; acc[0][2] += a[0]*b4.z; acc[0][3] += a[0]*b4.w;
            acc[1][0] += a[1]*b4.x; acc[1][1] += a[1]*b4.y; acc[1][2] += a[1]*b4.z; acc[1][3] += a[1]*b4.w;
            acc[2][0] += a[2]*b4.x; acc[2][1] += a[2]*b4.y; acc[2][2] += a[2]*b4.z; acc[2][3] += a[2]*b4.w;
            acc[3][0] += a[3]*b4.x; acc[3][1] += a[3]*b4.y; acc[3][2] += a[3]*b4.z; acc[3][3] += a[3]*b4.w;
        }
        __syncthreads();
    }

    #pragma unroll
    for (int i = 0; i < 4; i++) {
        float4 v4 = make_float4(acc[i][0], acc[i][1], acc[i][2], acc[i][3]);
        *reinterpret_cast<float4*>(&out[(size_t)(row0 + ty*4 + i) * H_ + tx*4]) = v4;
    }
}

// ---------------------------------------------------------------------------
// Kernel 2: flash attention, fp32. 64-query x 64-key tiles, online softmax.
// grid = (T/64, B), block = 256 (16x16). O accumulator 4x4 per thread.
// Smem: Qs[64][68] (scaled), KP[64][68] (K^T then P), Vs[64][68], m/l/alpha.
// ---------------------------------------------------------------------------
#define SS 68   // smem row stride (multiple of 4 for float4, offsets banks)

__global__ __launch_bounds__(256) void attn_kernel(float* __restrict__ out)
{
    extern __shared__ float sm[];
    float* Qs  = sm;                 // 64*SS
    float* KP  = Qs + 64*SS;         // 64*SS : K transposed [d][j], then P [i][j]
    float* Vs  = KP + 64*SS;         // 64*SS : [j][h]
    float* m_s = Vs + 64*SS;         // 64
    float* l_s = m_s + 64;           // 64
    float* a_s = l_s + 64;           // 64

    const int b   = blockIdx.y;
    const int qb  = gridDim.x - 1 - blockIdx.x;   // heavy tiles first
    const int tid = threadIdx.x;
    const int tx  = tid & 15;
    const int ty  = tid >> 4;
    const int lane = tid & 31;
    const int w    = tid >> 5;

    const float scale = 0.03125f;  // C^-0.5 = 1/32

    // load Q tile (pre-scaled)
    const float* qg = g_q + ((size_t)b * T_ + (size_t)qb * 64) * H_;
    for (int i = tid * 4; i < 64*64; i += 1024) {
        int r = i >> 6, c = i & 63;
        float4 v4 = *reinterpret_cast<const float4*>(&qg[r*64 + c]);
        Qs[r*SS + c + 0] = v4.x * scale;
        Qs[r*SS + c + 1] = v4.y * scale;
        Qs[r*SS + c + 2] = v4.z * scale;
        Qs[r*SS + c + 3] = v4.w * scale;
    }
    if (tid < 64) { m_s[tid] = -1e30f; l_s[tid] = 0.0f; }

    float acc[4][4] = {};
    __syncthreads();

    for (int kb = 0; kb <= qb; kb++) {
        const float* kg = g_k + ((size_t)b * T_ + (size_t)kb * 64) * H_;
        const float* vg = g_v + ((size_t)b * T_ + (size_t)kb * 64) * H_;

        // K transposed into KP: KP[d][j] = K[j][d]
        for (int i = tid; i < 64*64; i += 256) {
            int j = i >> 6, d = i & 63;
            KP[d*SS + j] = kg[i];
        }
        // V row-major
        for (int i = tid * 4; i < 64*64; i += 1024) {
            int j = i >> 6, h = i & 63;
            *reinterpret_cast<float4*>(&Vs[j*SS + h]) =
                *reinterpret_cast<const float4*>(&vg[i]);
        }
        __syncthreads();

        // S = (Q*scale) @ K^T   (4x4 per thread)
        float s[4][4] = {};
        #pragma unroll 8
        for (int d = 0; d < 64; d++) {
            float a[4];
            #pragma unroll
            for (int i = 0; i < 4; i++) a[i] = Qs[(ty*4 + i)*SS + d];
            float4 b4 = *reinterpret_cast<const float4*>(&KP[d*SS + tx*4]);
            #pragma unroll
            for (int i = 0; i < 4; i++) {
                s[i][0] += a[i]*b4.x; s[i][1] += a[i]*b4.y;
                s[i][2] += a[i]*b4.z; s[i][3] += a[i]*b4.w;
            }
        }
        // causal mask (diagonal tile only)
        if (kb == qb) {
            #pragma unroll
            for (int i = 0; i < 4; i++)
                #pragma unroll
                for (int j = 0; j < 4; j++)
                    if (tx*4 + j > ty*4 + i) s[i][j] = -1e30f;
        }
        __syncthreads();   // all K reads done; KP becomes P

        #pragma unroll
        for (int i = 0; i < 4; i++) {
            float4 v4 = make_float4(s[i][0], s[i][1], s[i][2], s[i][3]);
            *reinterpret_cast<float4*>(&KP[(ty*4 + i)*SS + tx*4]) = v4;
        }
        __syncthreads();

        // online softmax: warp w owns rows w*8..w*8+7; 4 lanes per row, 16 cols each
        {
            int row = w*8 + (lane & 7);
            int seg = lane >> 3;
            float* prow = &KP[row*SS + seg*16];
            float tmax = -1e30f;
            #pragma unroll
            for (int c = 0; c < 16; c++) tmax = fmaxf(tmax, prow[c]);
            tmax = fmaxf(tmax, __shfl_xor_sync(0xffffffff, tmax, 8));
            tmax = fmaxf(tmax, __shfl_xor_sync(0xffffffff, tmax, 16));
            float m_old = m_s[row];
            float m_new = fmaxf(m_old, tmax);
            float lsum = 0.0f;
            #pragma unroll
            for (int c = 0; c < 16; c++) {
                float p = __expf(prow[c] - m_new);
                prow[c] = p;
                lsum += p;
            }
            lsum += __shfl_xor_sync(0xffffffff, lsum, 8);
            lsum += __shfl_xor_sync(0xffffffff, lsum, 16);
            if (seg == 0) {
                float alpha = __expf(m_old - m_new);
                l_s[row] = l_s[row] * alpha + lsum;
                m_s[row] = m_new;
                a_s[row] = alpha;
            }
        }
        __syncthreads();

        // rescale O and accumulate P @ V
        float alr[4];
        #pragma unroll
        for (int i = 0; i < 4; i++) alr[i] = a_s[ty*4 + i];
        #pragma unroll
        for (int i = 0; i < 4; i++)
            #pragma unroll
            for (int j = 0; j < 4; j++)
                acc[i][j] *= alr[i];

        #pragma unroll 8
        for (int j = 0; j < 64; j++) {
            float a[4];
            #pragma unroll
            for (int i = 0; i < 4; i++) a[i] = KP[(ty*4 + i)*SS + j];
            float4 b4 = *reinterpret_cast<const float4*>(&Vs[j*SS + tx*4]);
            #pragma unroll
            for (int i = 0; i < 4; i++) {
                acc[i][0] += a[i]*b4.x; acc[i][1] += a[i]*b4.y;
                acc[i][2] += a[i]*b4.z; acc[i][3] += a[i]*b4.w;
            }
        }
        __syncthreads();   // protect KP/Vs for next iteration's loads
    }

    // final normalize + store
    float* og = out + ((size_t)b * T_ + (size_t)qb * 64) * H_;
    #pragma unroll
    for (int i = 0; i < 4; i++) {
        float inv = 1.0f / l_s[ty*4 + i];
        float4 v4 = make_float4(acc[i][0]*inv, acc[i][1]*inv,
                                acc[i][2]*inv, acc[i][3]*inv);
        *reinterpret_cast<float4*>(&og[(ty*4 + i)*64 + tx*4]) = v4;
    }
}

// ---------------------------------------------------------------------------
extern "C" void kernel_launch(void* const* d_in, const int* in_sizes, int n_in,
                              void* d_out, int out_size)
{
    const float* x  = (const float*)d_in[0];
    const float* Wk = (const float*)d_in[1];
    const float* Wq = (const float*)d_in[2];
    const float* Wv = (const float*)d_in[3];
    float* out = (float*)d_out;

    // QKV projections
    qkv_kernel<<<dim3((B_*T_)/64, 3), 256>>>(x, Wk, Wq, Wv);

    // flash attention
    const int smem_bytes = (3 * 64 * SS + 3 * 64) * (int)sizeof(float);
    cudaFuncSetAttribute(attn_kernel,
                         cudaFuncAttributeMaxDynamicSharedMemorySize, smem_bytes);
    attn_kernel<<<dim3(T_/64, B_), 256, smem_bytes>>>(out);
}

// round 2
// speedup vs baseline: 1.6627x; 1.6627x over previous
#include <cuda_runtime.h>
#include <cstdint>

#define B_ 4
#define T_ 4096
#define C_ 1024
#define H_ 64

__device__ float g_q[B_*T_*H_];
__device__ float g_k[B_*T_*H_];
__device__ float g_v[B_*T_*H_];

__device__ __forceinline__ uint32_t f2tf32(float x) {
    uint32_t r;
    asm("cvt.rna.tf32.f32 %0, %1;" : "=r"(r) : "f"(x));
    return r;
}

__device__ __forceinline__ void mma_tf32(float c[4], const uint32_t a[4],
                                         uint32_t b0, uint32_t b1) {
    asm volatile(
        "mma.sync.aligned.m16n8k8.row.col.f32.tf32.tf32.f32 "
        "{%0,%1,%2,%3}, {%4,%5,%6,%7}, {%8,%9}, {%0,%1,%2,%3};"
        : "+f"(c[0]), "+f"(c[1]), "+f"(c[2]), "+f"(c[3])
        : "r"(a[0]), "r"(a[1]), "r"(a[2]), "r"(a[3]), "r"(b0), "r"(b1));
}

// ---------------------------------------------------------------------------
// Kernel 1: QKV projection, tf32 mma. Y = X @ W. X:[16384,1024], W:[1024,64].
// block 128 thr (4 warps), tile 128x64, warp tile 32x64. K chunks of 32.
// ---------------------------------------------------------------------------
#define XS 44   // smem stride (words): conflict-free frag loads, 16B aligned

__global__ __launch_bounds__(128) void qkv_kernel(
    const float* __restrict__ x,
    const float* __restrict__ Wk,
    const float* __restrict__ Wq,
    const float* __restrict__ Wv)
{
    __shared__ uint32_t Xs[128 * XS];
    __shared__ uint32_t Ws[64 * XS];

    const float* W;
    float* out;
    if (blockIdx.y == 0)      { W = Wk; out = g_k; }
    else if (blockIdx.y == 1) { W = Wq; out = g_q; }
    else                      { W = Wv; out = g_v; }

    const int row0 = blockIdx.x * 128;
    const int tid  = threadIdx.x;
    const int w    = tid >> 5;
    const int lane = tid & 31;
    const int g    = lane >> 2;     // groupID
    const int q    = lane & 3;      // thread-in-group

    float acc[2][8][4] = {};

    for (int k0 = 0; k0 < C_; k0 += 32) {
        // X tile [128][32] -> tf32
        for (int i = tid * 4; i < 128 * 32; i += 512) {
            int r = i >> 5, c = i & 31;
            float4 v4 = *reinterpret_cast<const float4*>(&x[(size_t)(row0 + r) * C_ + k0 + c]);
            uint4 u4 = make_uint4(f2tf32(v4.x), f2tf32(v4.y), f2tf32(v4.z), f2tf32(v4.w));
            *reinterpret_cast<uint4*>(&Xs[r * XS + c]) = u4;
        }
        // W tile transposed: Ws[n][k] = W[k0+k][n] -> tf32
        for (int i = tid; i < 32 * 64; i += 128) {
            int kk = i >> 6, n = i & 63;
            Ws[n * XS + kk] = f2tf32(W[(size_t)(k0 + kk) * H_ + n]);
        }
        __syncthreads();

        #pragma unroll
        for (int ks = 0; ks < 4; ks++) {
            uint32_t bn[8][2];
            #pragma unroll
            for (int n = 0; n < 8; n++) {
                bn[n][0] = Ws[(n * 8 + g) * XS + ks * 8 + q];
                bn[n][1] = Ws[(n * 8 + g) * XS + ks * 8 + q + 4];
            }
            #pragma unroll
            for (int m = 0; m < 2; m++) {
                int row = w * 32 + m * 16 + g;
                uint32_t a[4];
                a[0] = Xs[row * XS + ks * 8 + q];
                a[1] = Xs[(row + 8) * XS + ks * 8 + q];
                a[2] = Xs[row * XS + ks * 8 + q + 4];
                a[3] = Xs[(row + 8) * XS + ks * 8 + q + 4];
                #pragma unroll
                for (int n = 0; n < 8; n++)
                    mma_tf32(acc[m][n], a, bn[n][0], bn[n][1]);
            }
        }
        __syncthreads();
    }

    #pragma unroll
    for (int m = 0; m < 2; m++) {
        int row = row0 + w * 32 + m * 16 + g;
        #pragma unroll
        for (int n = 0; n < 8; n++) {
            int col = n * 8 + q * 2;
            *reinterpret_cast<float2*>(&out[(size_t)row * H_ + col]) =
                make_float2(acc[m][n][0], acc[m][n][1]);
            *reinterpret_cast<float2*>(&out[(size_t)(row + 8) * H_ + col]) =
                make_float2(acc[m][n][2], acc[m][n][3]);
        }
    }
}

// ---------------------------------------------------------------------------
// Kernel 2: flash attention, tf32 mma. 64 queries / CTA, 4 warps x 16 rows,
// 64-key tiles. Q frags in regs; K/Vt in smem (tf32); P via per-warp smem.
// ---------------------------------------------------------------------------
#define SS 68   // smem stride (words)

__global__ __launch_bounds__(128) void attn_kernel(float* __restrict__ out)
{
    extern __shared__ uint32_t sm[];
    uint32_t* Ks  = sm;               // [64][SS] K[j][d] (tf32)
    uint32_t* Vts = Ks + 64 * SS;     // [64][SS] V^T[h][j] (tf32)
    uint32_t* Ps  = Vts + 64 * SS;    // [64][SS] Q staging, then per-warp P

    const int b   = blockIdx.y;
    const int qb  = gridDim.x - 1 - blockIdx.x;   // heavy tiles first
    const int tid = threadIdx.x;
    const int w   = tid >> 5;
    const int lane = tid & 31;
    const int g   = lane >> 2;
    const int q   = lane & 3;

    const float scale = 0.03125f;   // C^-0.5

    // stage Q (scaled, tf32) into Ps
    const float* qg = g_q + ((size_t)b * T_ + (size_t)qb * 64) * H_;
    for (int i = tid * 4; i < 64 * 64; i += 512) {
        int r = i >> 6, c = i & 63;
        float4 v4 = *reinterpret_cast<const float4*>(&qg[r * 64 + c]);
        uint4 u4 = make_uint4(f2tf32(v4.x * scale), f2tf32(v4.y * scale),
                              f2tf32(v4.z * scale), f2tf32(v4.w * scale));
        *reinterpret_cast<uint4*>(&Ps[r * SS + c]) = u4;
    }
    __syncthreads();

    // extract Q frags: warp w owns rows w*16 .. w*16+15
    uint32_t qa[8][4];
    #pragma unroll
    for (int kk = 0; kk < 8; kk++) {
        int row = w * 16 + g;
        qa[kk][0] = Ps[row * SS + kk * 8 + q];
        qa[kk][1] = Ps[(row + 8) * SS + kk * 8 + q];
        qa[kk][2] = Ps[row * SS + kk * 8 + q + 4];
        qa[kk][3] = Ps[(row + 8) * SS + kk * 8 + q + 4];
    }

    float o[8][4] = {};
    float m0 = -1e30f, m1 = -1e30f, l0 = 0.0f, l1 = 0.0f;

    for (int kb = 0; kb <= qb; kb++) {
        const float* kg = g_k + ((size_t)b * T_ + (size_t)kb * 64) * H_;
        const float* vg = g_v + ((size_t)b * T_ + (size_t)kb * 64) * H_;

        __syncthreads();   // protect Ks/Vts/Ps from previous iteration readers
        for (int i = tid * 4; i < 64 * 64; i += 512) {
            int r = i >> 6, c = i & 63;
            float4 v4 = *reinterpret_cast<const float4*>(&kg[r * 64 + c]);
            uint4 u4 = make_uint4(f2tf32(v4.x), f2tf32(v4.y), f2tf32(v4.z), f2tf32(v4.w));
            *reinterpret_cast<uint4*>(&Ks[r * SS + c]) = u4;
        }
        for (int i = tid; i < 64 * 64; i += 128) {
            int j = i >> 6, h = i & 63;
            Vts[h * SS + j] = f2tf32(vg[i]);
        }
        __syncthreads();

        // S = Q @ K^T  (16x64 per warp)
        float s[8][4] = {};
        #pragma unroll
        for (int kk = 0; kk < 8; kk++) {
            #pragma unroll
            for (int n = 0; n < 8; n++) {
                uint32_t b0 = Ks[(n * 8 + g) * SS + kk * 8 + q];
                uint32_t b1 = Ks[(n * 8 + g) * SS + kk * 8 + q + 4];
                mma_tf32(s[n], qa[kk], b0, b1);
            }
        }

        // causal mask (diagonal tile)
        if (kb == qb) {
            int r0 = w * 16 + g;
            #pragma unroll
            for (int n = 0; n < 8; n++) {
                int c0 = n * 8 + q * 2;
                if (c0     > r0)     s[n][0] = -1e30f;
                if (c0 + 1 > r0)     s[n][1] = -1e30f;
                if (c0     > r0 + 8) s[n][2] = -1e30f;
                if (c0 + 1 > r0 + 8) s[n][3] = -1e30f;
            }
        }

        // online softmax (rows: r0 = w*16+g, r1 = r0+8)
        float tmax0 = -1e30f, tmax1 = -1e30f;
        #pragma unroll
        for (int n = 0; n < 8; n++) {
            tmax0 = fmaxf(tmax0, fmaxf(s[n][0], s[n][1]));
            tmax1 = fmaxf(tmax1, fmaxf(s[n][2], s[n][3]));
        }
        tmax0 = fmaxf(tmax0, __shfl_xor_sync(0xffffffff, tmax0, 1));
        tmax0 = fmaxf(tmax0, __shfl_xor_sync(0xffffffff, tmax0, 2));
        tmax1 = fmaxf(tmax1, __shfl_xor_sync(0xffffffff, tmax1, 1));
        tmax1 = fmaxf(tmax1, __shfl_xor_sync(0xffffffff, tmax1, 2));

        float m0n = fmaxf(m0, tmax0);
        float m1n = fmaxf(m1, tmax1);
        float al0 = __expf(m0 - m0n);
        float al1 = __expf(m1 - m1n);

        float sum0 = 0.0f, sum1 = 0.0f;
        #pragma unroll
        for (int n = 0; n < 8; n++) {
            s[n][0] = __expf(s[n][0] - m0n);
            s[n][1] = __expf(s[n][1] - m0n);
            s[n][2] = __expf(s[n][2] - m1n);
            s[n][3] = __expf(s[n][3] - m1n);
            sum0 += s[n][0] + s[n][1];
            sum1 += s[n][2] + s[n][3];
        }
        sum0 += __shfl_xor_sync(0xffffffff, sum0, 1);
        sum0 += __shfl_xor_sync(0xffffffff, sum0, 2);
        sum1 += __shfl_xor_sync(0xffffffff, sum1, 1);
        sum1 += __shfl_xor_sync(0xffffffff, sum1, 2);

        l0 = l0 * al0 + sum0;  m0 = m0n;
        l1 = l1 * al1 + sum1;  m1 = m1n;

        #pragma unroll
        for (int n = 0; n < 8; n++) {
            o[n][0] *= al0; o[n][1] *= al0;
            o[n][2] *= al1; o[n][3] *= al1;
        }

        // P -> tf32 A-layout via per-warp smem roundtrip
        {
            int row = w * 16 + g;
            #pragma unroll
            for (int n = 0; n < 8; n++) {
                int col = n * 8 + q * 2;
                *reinterpret_cast<uint2*>(&Ps[row * SS + col]) =
                    make_uint2(f2tf32(s[n][0]), f2tf32(s[n][1]));
                *reinterpret_cast<uint2*>(&Ps[(row + 8) * SS + col]) =
                    make_uint2(f2tf32(s[n][2]), f2tf32(s[n][3]));
            }
        }
        __syncwarp();

        // O += P @ V   (B = V^T[h][j])
        #pragma unroll
        for (int kk = 0; kk < 8; kk++) {
            int row = w * 16 + g;
            uint32_t pa[4];
            pa[0] = Ps[row * SS + kk * 8 + q];
            pa[1] = Ps[(row + 8) * SS + kk * 8 + q];
            pa[2] = Ps[row * SS + kk * 8 + q + 4];
            pa[3] = Ps[(row + 8) * SS + kk * 8 + q + 4];
            #pragma unroll
            for (int n = 0; n < 8; n++) {
                uint32_t b0 = Vts[(n * 8 + g) * SS + kk * 8 + q];
                uint32_t b1 = Vts[(n * 8 + g) * SS + kk * 8 + q + 4];
                mma_tf32(o[n], pa, b0, b1);
            }
        }
    }

    // normalize + store
    float inv0 = 1.0f / l0;
    float inv1 = 1.0f / l1;
    float* og = out + ((size_t)b * T_ + (size_t)qb * 64 + w * 16) * H_;
    #pragma unroll
    for (int n = 0; n < 8; n++) {
        int col = n * 8 + q * 2;
        *reinterpret_cast<float2*>(&og[g * H_ + col]) =
            make_float2(o[n][0] * inv0, o[n][1] * inv0);
        *reinterpret_cast<float2*>(&og[(g + 8) * H_ + col]) =
            make_float2(o[n][2] * inv1, o[n][3] * inv1);
    }
}

// ---------------------------------------------------------------------------
extern "C" void kernel_launch(void* const* d_in, const int* in_sizes, int n_in,
                              void* d_out, int out_size)
{
    const float* x  = (const float*)d_in[0];
    const float* Wk = (const float*)d_in[1];
    const float* Wq = (const float*)d_in[2];
    const float* Wv = (const float*)d_in[3];
    float* out = (float*)d_out;

    qkv_kernel<<<dim3((B_*T_)/128, 3), 128>>>(x, Wk, Wq, Wv);

    const int smem_bytes = 3 * 64 * SS * (int)sizeof(uint32_t);
    cudaFuncSetAttribute(attn_kernel,
                         cudaFuncAttributeMaxDynamicSharedMemorySize, smem_bytes);
    attn_kernel<<<dim3(T_/64, B_), 128, smem_bytes>>>(out);
}

// round 3
// speedup vs baseline: 2.7041x; 1.6263x over previous
#include <cuda_runtime.h>
#include <cstdint>

#define B_ 4
#define T_ 4096
#define C_ 1024
#define H_ 64

#define NCHUNK 4        // max split-K chunks per q-tile
#define CHUNK_TILES 16  // k-tiles per chunk (16*64 = 1024 keys)

__device__ float g_q[B_*T_*H_];
__device__ float g_k[B_*T_*H_];
__device__ float g_v[B_*T_*H_];

// split-K partials: O (unnormalized), m, l
__device__ float g_po[B_*NCHUNK*64*64*H_];   // [b][c][qt][row][h]  16.8 MB
__device__ float g_pm[B_*NCHUNK*64*64];      // [b][c][qt][row]
__device__ float g_pl[B_*NCHUNK*64*64];

__device__ __forceinline__ uint32_t f2tf32(float x) {
    uint32_t r;
    asm("cvt.rna.tf32.f32 %0, %1;" : "=r"(r) : "f"(x));
    return r;
}

__device__ __forceinline__ void mma_tf32(float c[4], const uint32_t a[4],
                                         uint32_t b0, uint32_t b1) {
    asm volatile(
        "mma.sync.aligned.m16n8k8.row.col.f32.tf32.tf32.f32 "
        "{%0,%1,%2,%3}, {%4,%5,%6,%7}, {%8,%9}, {%0,%1,%2,%3};"
        : "+f"(c[0]), "+f"(c[1]), "+f"(c[2]), "+f"(c[3])
        : "r"(a[0]), "r"(a[1]), "r"(a[2]), "r"(a[3]), "r"(b0), "r"(b1));
}

// ---------------------------------------------------------------------------
// Kernel 1: QKV projection, tf32 mma (unchanged from R2).
// ---------------------------------------------------------------------------
#define XS 44

__global__ __launch_bounds__(128) void qkv_kernel(
    const float* __restrict__ x,
    const float* __restrict__ Wk,
    const float* __restrict__ Wq,
    const float* __restrict__ Wv)
{
    __shared__ uint32_t Xs[128 * XS];
    __shared__ uint32_t Ws[64 * XS];

    const float* W;
    float* out;
    if (blockIdx.y == 0)      { W = Wk; out = g_k; }
    else if (blockIdx.y == 1) { W = Wq; out = g_q; }
    else                      { W = Wv; out = g_v; }

    const int row0 = blockIdx.x * 128;
    const int tid  = threadIdx.x;
    const int w    = tid >> 5;
    const int lane = tid & 31;
    const int g    = lane >> 2;
    const int q    = lane & 3;

    float acc[2][8][4] = {};

    for (int k0 = 0; k0 < C_; k0 += 32) {
        for (int i = tid * 4; i < 128 * 32; i += 512) {
            int r = i >> 5, c = i & 31;
            float4 v4 = *reinterpret_cast<const float4*>(&x[(size_t)(row0 + r) * C_ + k0 + c]);
            uint4 u4 = make_uint4(f2tf32(v4.x), f2tf32(v4.y), f2tf32(v4.z), f2tf32(v4.w));
            *reinterpret_cast<uint4*>(&Xs[r * XS + c]) = u4;
        }
        for (int i = tid; i < 32 * 64; i += 128) {
            int kk = i >> 6, n = i & 63;
            Ws[n * XS + kk] = f2tf32(W[(size_t)(k0 + kk) * H_ + n]);
        }
        __syncthreads();

        #pragma unroll
        for (int ks = 0; ks < 4; ks++) {
            uint32_t bn[8][2];
            #pragma unroll
            for (int n = 0; n < 8; n++) {
                bn[n][0] = Ws[(n * 8 + g) * XS + ks * 8 + q];
                bn[n][1] = Ws[(n * 8 + g) * XS + ks * 8 + q + 4];
            }
            #pragma unroll
            for (int m = 0; m < 2; m++) {
                int row = w * 32 + m * 16 + g;
                uint32_t a[4];
                a[0] = Xs[row * XS + ks * 8 + q];
                a[1] = Xs[(row + 8) * XS + ks * 8 + q];
                a[2] = Xs[row * XS + ks * 8 + q + 4];
                a[3] = Xs[(row + 8) * XS + ks * 8 + q + 4];
                #pragma unroll
                for (int n = 0; n < 8; n++)
                    mma_tf32(acc[m][n], a, bn[n][0], bn[n][1]);
            }
        }
        __syncthreads();
    }

    #pragma unroll
    for (int m = 0; m < 2; m++) {
        int row = row0 + w * 32 + m * 16 + g;
        #pragma unroll
        for (int n = 0; n < 8; n++) {
            int col = n * 8 + q * 2;
            *reinterpret_cast<float2*>(&out[(size_t)row * H_ + col]) =
                make_float2(acc[m][n][0], acc[m][n][1]);
            *reinterpret_cast<float2*>(&out[(size_t)(row + 8) * H_ + col]) =
                make_float2(acc[m][n][2], acc[m][n][3]);
        }
    }
}

// ---------------------------------------------------------------------------
// Kernel 2: flash attention partial pass (split-K).
// grid = (64 qtiles, NCHUNK, B). CTA processes k-tiles [c*16, min(qt, c*16+15)].
// Writes unnormalized O, m, l partials.
// ---------------------------------------------------------------------------
#define SS 68

__global__ __launch_bounds__(128) void attn_part_kernel()
{
    extern __shared__ uint32_t sm[];
    uint32_t* Ks  = sm;
    uint32_t* Vts = Ks + 64 * SS;
    uint32_t* Ps  = Vts + 64 * SS;

    const int qt = blockIdx.x;
    const int c  = blockIdx.y;
    const int b  = blockIdx.z;

    const int kb_lo = c * CHUNK_TILES;
    if (kb_lo > qt) return;                       // empty chunk
    const int kb_hi = min(qt, kb_lo + CHUNK_TILES - 1);

    const int tid = threadIdx.x;
    const int w   = tid >> 5;
    const int lane = tid & 31;
    const int g   = lane >> 2;
    const int q   = lane & 3;

    const float scale = 0.03125f;

    const float* qg = g_q + ((size_t)b * T_ + (size_t)qt * 64) * H_;
    for (int i = tid * 4; i < 64 * 64; i += 512) {
        int r = i >> 6, cc = i & 63;
        float4 v4 = *reinterpret_cast<const float4*>(&qg[r * 64 + cc]);
        uint4 u4 = make_uint4(f2tf32(v4.x * scale), f2tf32(v4.y * scale),
                              f2tf32(v4.z * scale), f2tf32(v4.w * scale));
        *reinterpret_cast<uint4*>(&Ps[r * SS + cc]) = u4;
    }
    __syncthreads();

    uint32_t qa[8][4];
    #pragma unroll
    for (int kk = 0; kk < 8; kk++) {
        int row = w * 16 + g;
        qa[kk][0] = Ps[row * SS + kk * 8 + q];
        qa[kk][1] = Ps[(row + 8) * SS + kk * 8 + q];
        qa[kk][2] = Ps[row * SS + kk * 8 + q + 4];
        qa[kk][3] = Ps[(row + 8) * SS + kk * 8 + q + 4];
    }

    float o[8][4] = {};
    float m0 = -1e30f, m1 = -1e30f, l0 = 0.0f, l1 = 0.0f;

    for (int kb = kb_lo; kb <= kb_hi; kb++) {
        const float* kg = g_k + ((size_t)b * T_ + (size_t)kb * 64) * H_;
        const float* vg = g_v + ((size_t)b * T_ + (size_t)kb * 64) * H_;

        __syncthreads();
        for (int i = tid * 4; i < 64 * 64; i += 512) {
            int r = i >> 6, cc = i & 63;
            float4 v4 = *reinterpret_cast<const float4*>(&kg[r * 64 + cc]);
            uint4 u4 = make_uint4(f2tf32(v4.x), f2tf32(v4.y), f2tf32(v4.z), f2tf32(v4.w));
            *reinterpret_cast<uint4*>(&Ks[r * SS + cc]) = u4;
        }
        for (int i = tid; i < 64 * 64; i += 128) {
            int j = i >> 6, h = i & 63;
            Vts[h * SS + j] = f2tf32(vg[i]);
        }
        __syncthreads();

        float s[8][4] = {};
        #pragma unroll
        for (int kk = 0; kk < 8; kk++) {
            #pragma unroll
            for (int n = 0; n < 8; n++) {
                uint32_t b0 = Ks[(n * 8 + g) * SS + kk * 8 + q];
                uint32_t b1 = Ks[(n * 8 + g) * SS + kk * 8 + q + 4];
                mma_tf32(s[n], qa[kk], b0, b1);
            }
        }

        if (kb == qt) {
            int r0 = w * 16 + g;
            #pragma unroll
            for (int n = 0; n < 8; n++) {
                int c0 = n * 8 + q * 2;
                if (c0     > r0)     s[n][0] = -1e30f;
                if (c0 + 1 > r0)     s[n][1] = -1e30f;
                if (c0     > r0 + 8) s[n][2] = -1e30f;
                if (c0 + 1 > r0 + 8) s[n][3] = -1e30f;
            }
        }

        float tmax0 = -1e30f, tmax1 = -1e30f;
        #pragma unroll
        for (int n = 0; n < 8; n++) {
            tmax0 = fmaxf(tmax0, fmaxf(s[n][0], s[n][1]));
            tmax1 = fmaxf(tmax1, fmaxf(s[n][2], s[n][3]));
        }
        tmax0 = fmaxf(tmax0, __shfl_xor_sync(0xffffffff, tmax0, 1));
        tmax0 = fmaxf(tmax0, __shfl_xor_sync(0xffffffff, tmax0, 2));
        tmax1 = fmaxf(tmax1, __shfl_xor_sync(0xffffffff, tmax1, 1));
        tmax1 = fmaxf(tmax1, __shfl_xor_sync(0xffffffff, tmax1, 2));

        float m0n = fmaxf(m0, tmax0);
        float m1n = fmaxf(m1, tmax1);
        float al0 = __expf(m0 - m0n);
        float al1 = __expf(m1 - m1n);

        float sum0 = 0.0f, sum1 = 0.0f;
        #pragma unroll
        for (int n = 0; n < 8; n++) {
            s[n][0] = __expf(s[n][0] - m0n);
            s[n][1] = __expf(s[n][1] - m0n);
            s[n][2] = __expf(s[n][2] - m1n);
            s[n][3] = __expf(s[n][3] - m1n);
            sum0 += s[n][0] + s[n][1];
            sum1 += s[n][2] + s[n][3];
        }
        sum0 += __shfl_xor_sync(0xffffffff, sum0, 1);
        sum0 += __shfl_xor_sync(0xffffffff, sum0, 2);
        sum1 += __shfl_xor_sync(0xffffffff, sum1, 1);
        sum1 += __shfl_xor_sync(0xffffffff, sum1, 2);

        l0 = l0 * al0 + sum0;  m0 = m0n;
        l1 = l1 * al1 + sum1;  m1 = m1n;

        #pragma unroll
        for (int n = 0; n < 8; n++) {
            o[n][0] *= al0; o[n][1] *= al0;
            o[n][2] *= al1; o[n][3] *= al1;
        }

        {
            int row = w * 16 + g;
            #pragma unroll
            for (int n = 0; n < 8; n++) {
                int col = n * 8 + q * 2;
                *reinterpret_cast<uint2*>(&Ps[row * SS + col]) =
                    make_uint2(f2tf32(s[n][0]), f2tf32(s[n][1]));
                *reinterpret_cast<uint2*>(&Ps[(row + 8) * SS + col]) =
                    make_uint2(f2tf32(s[n][2]), f2tf32(s[n][3]));
            }
        }
        __syncwarp();

        #pragma unroll
        for (int kk = 0; kk < 8; kk++) {
            int row = w * 16 + g;
            uint32_t pa[4];
            pa[0] = Ps[row * SS + kk * 8 + q];
            pa[1] = Ps[(row + 8) * SS + kk * 8 + q];
            pa[2] = Ps[row * SS + kk * 8 + q + 4];
            pa[3] = Ps[(row + 8) * SS + kk * 8 + q + 4];
            #pragma unroll
            for (int n = 0; n < 8; n++) {
                uint32_t b0 = Vts[(n * 8 + g) * SS + kk * 8 + q];
                uint32_t b1 = Vts[(n * 8 + g) * SS + kk * 8 + q + 4];
                mma_tf32(o[n], pa, b0, b1);
            }
        }
    }

    // store partials (unnormalized O, m, l)
    const size_t pbase = ((size_t)(b * NCHUNK + c) * 64 + qt);
    float* po = g_po + pbase * 64 * H_;
    float* pm = g_pm + pbase * 64;
    float* pl = g_pl + pbase * 64;

    const int r0 = w * 16 + g;
    #pragma unroll
    for (int n = 0; n < 8; n++) {
        int col = n * 8 + q * 2;
        *reinterpret_cast<float2*>(&po[r0 * H_ + col]) = make_float2(o[n][0], o[n][1]);
        *reinterpret_cast<float2*>(&po[(r0 + 8) * H_ + col]) = make_float2(o[n][2], o[n][3]);
    }
    if (q == 0) {
        pm[r0] = m0; pl[r0] = l0;
        pm[r0 + 8] = m1; pl[r0 + 8] = l1;
    }
}

// ---------------------------------------------------------------------------
// Kernel 3: merge split-K partials.
// grid = (64 qtiles, B), block 256: thread t handles row=t/4, cols (t%4)*16..
// ---------------------------------------------------------------------------
__global__ __launch_bounds__(256) void attn_merge_kernel(float* __restrict__ out)
{
    const int qt = blockIdx.x;
    const int b  = blockIdx.y;
    const int t  = threadIdx.x;
    const int row = t >> 2;
    const int c0  = (t & 3) * 16;

    const int nc = qt / CHUNK_TILES + 1;   // valid chunks

    float m[NCHUNK], l[NCHUNK];
    float M = -1e30f;
    #pragma unroll
    for (int c = 0; c < NCHUNK; c++) {
        if (c < nc) {
            size_t pbase = ((size_t)(b * NCHUNK + c) * 64 + qt);
            m[c] = g_pm[pbase * 64 + row];
            l[c] = g_pl[pbase * 64 + row];
            M = fmaxf(M, m[c]);
        }
    }
    float L = 0.0f, sc[NCHUNK];
    #pragma unroll
    for (int c = 0; c < NCHUNK; c++) {
        if (c < nc) {
            sc[c] = __expf(m[c] - M);
            L += l[c] * sc[c];
        }
    }
    const float invL = 1.0f / L;

    float* og = out + ((size_t)b * T_ + (size_t)qt * 64 + row) * H_ + c0;

    #pragma unroll
    for (int j = 0; j < 16; j += 4) {
        float4 acc = make_float4(0.f, 0.f, 0.f, 0.f);
        #pragma unroll
        for (int c = 0; c < NCHUNK; c++) {
            if (c < nc) {
                size_t pbase = ((size_t)(b * NCHUNK + c) * 64 + qt);
                const float* po = g_po + (pbase * 64 + row) * H_ + c0 + j;
                float4 v4 = *reinterpret_cast<const float4*>(po);
                acc.x += v4.x * sc[c]; acc.y += v4.y * sc[c];
                acc.z += v4.z * sc[c]; acc.w += v4.w * sc[c];
            }
        }
        acc.x *= invL; acc.y *= invL; acc.z *= invL; acc.w *= invL;
        *reinterpret_cast<float4*>(&og[j]) = acc;
    }
}

// ---------------------------------------------------------------------------
extern "C" void kernel_launch(void* const* d_in, const int* in_sizes, int n_in,
                              void* d_out, int out_size)
{
    const float* x  = (const float*)d_in[0];
    const float* Wk = (const float*)d_in[1];
    const float* Wq = (const float*)d_in[2];
    const float* Wv = (const float*)d_in[3];
    float* out = (float*)d_out;

    qkv_kernel<<<dim3((B_*T_)/128, 3), 128>>>(x, Wk, Wq, Wv);

    const int smem_bytes = 3 * 64 * SS * (int)sizeof(uint32_t);
    cudaFuncSetAttribute(attn_part_kernel,
                         cudaFuncAttributeMaxDynamicSharedMemorySize, smem_bytes);
    attn_part_kernel<<<dim3(64, NCHUNK, B_), 128, smem_bytes>>>();

    attn_merge_kernel<<<dim3(64, B_), 256>>>(out);
}

// round 4
// speedup vs baseline: 4.4456x; 1.6440x over previous
#include <cuda_runtime.h>
#include <cstdint>

#define B_ 4
#define T_ 4096
#define C_ 1024
#define H_ 64

#define NCHUNK 4
#define CHUNK_TILES 16

__device__ float g_q[B_*T_*H_];
__device__ float g_k[B_*T_*H_];
__device__ float g_vt[B_*H_*T_];          // V transposed: [b][h][t]
__device__ uint32_t g_wt[3*64*1024];      // [sel][n][k] tf32 bits, sel 0=k,1=q,2=v

__device__ float g_po[B_*NCHUNK*64*64*H_];
__device__ float g_pm[B_*NCHUNK*64*64];
__device__ float g_pl[B_*NCHUNK*64*64];

__device__ __forceinline__ uint32_t f2tf32(float x) {
    uint32_t r;
    asm("cvt.rna.tf32.f32 %0, %1;" : "=r"(r) : "f"(x));
    return r;
}

__device__ __forceinline__ void mma_tf32(float c[4], const uint32_t a[4],
                                         uint32_t b0, uint32_t b1) {
    asm volatile(
        "mma.sync.aligned.m16n8k8.row.col.f32.tf32.tf32.f32 "
        "{%0,%1,%2,%3}, {%4,%5,%6,%7}, {%8,%9}, {%0,%1,%2,%3};"
        : "+f"(c[0]), "+f"(c[1]), "+f"(c[2]), "+f"(c[3])
        : "r"(a[0]), "r"(a[1]), "r"(a[2]), "r"(a[3]), "r"(b0), "r"(b1));
}

__device__ __forceinline__ void cp16(uint32_t dst, const void* src) {
    asm volatile("cp.async.cg.shared.global [%0], [%1], 16;" :: "r"(dst), "l"(src));
}

// ---------------------------------------------------------------------------
// Kernel 0: convert W -> tf32, transposed [n][k]
// ---------------------------------------------------------------------------
__global__ __launch_bounds__(256) void wconv_kernel(
    const float* __restrict__ Wk, const float* __restrict__ Wq,
    const float* __restrict__ Wv)
{
    int idx = blockIdx.x * 256 + threadIdx.x;     // 0 .. 196607
    int wi = idx >> 16;
    int r  = idx & 65535;
    int k  = r >> 6;
    int n  = r & 63;
    const float* W = (wi == 0) ? Wk : ((wi == 1) ? Wq : Wv);
    g_wt[((size_t)wi*64 + n)*1024 + k] = f2tf32(W[k*64 + n]);
}

// ---------------------------------------------------------------------------
// Kernel 1: fused QKV. CTA = 64 rows x 192 cols (K|Q|V). 4 warps, warp owns
// 48-col n-slice over all 64 rows. cp.async double-buffered K chunks of 32.
// ---------------------------------------------------------------------------
#define XST 36
#define WST 36
#define XBUF (64*XST)
#define WBUF (192*WST)

__global__ __launch_bounds__(128) void qkv_kernel(const float* __restrict__ x)
{
    extern __shared__ float smf[];
    float*    Xs = smf;                                   // [2][XBUF]
    uint32_t* Ws = (uint32_t*)(smf + 2*XBUF);             // [2][WBUF]

    const int row0 = blockIdx.x * 64;
    const int tid  = threadIdx.x;
    const int w    = tid >> 5;
    const int lane = tid & 31;
    const int g    = lane >> 2;
    const int q    = lane & 3;

    float acc[4][6][4] = {};

    // prefetch chunk 0
    {
        const int k0 = 0;
        #pragma unroll
        for (int j = 0; j < 4; j++) {
            int idx = tid + 128*j;
            int r = idx >> 3, c4 = (idx & 7) * 4;
            cp16((uint32_t)__cvta_generic_to_shared(&Xs[r*XST + c4]),
                 &x[(size_t)(row0 + r)*C_ + k0 + c4]);
        }
        #pragma unroll
        for (int j = 0; j < 12; j++) {
            int idx = tid + 128*j;
            int r = idx >> 3, c4 = (idx & 7) * 4;
            cp16((uint32_t)__cvta_generic_to_shared(&Ws[r*WST + c4]),
                 &g_wt[(size_t)r*1024 + k0 + c4]);
        }
        asm volatile("cp.async.commit_group;");
    }

    for (int ch = 0; ch < 32; ch++) {
        const int p = ch & 1;
        if (ch + 1 < 32) {
            const int k0 = (ch + 1) * 32;
            const int pn = p ^ 1;
            #pragma unroll
            for (int j = 0; j < 4; j++) {
                int idx = tid + 128*j;
                int r = idx >> 3, c4 = (idx & 7) * 4;
                cp16((uint32_t)__cvta_generic_to_shared(&Xs[pn*XBUF + r*XST + c4]),
                     &x[(size_t)(row0 + r)*C_ + k0 + c4]);
            }
            #pragma unroll
            for (int j = 0; j < 12; j++) {
                int idx = tid + 128*j;
                int r = idx >> 3, c4 = (idx & 7) * 4;
                cp16((uint32_t)__cvta_generic_to_shared(&Ws[pn*WBUF + r*WST + c4]),
                     &g_wt[(size_t)r*1024 + k0 + c4]);
            }
            asm volatile("cp.async.commit_group;");
            asm volatile("cp.async.wait_group 1;");
        } else {
            asm volatile("cp.async.wait_group 0;");
        }
        __syncthreads();

        const float*    Xc = Xs + p*XBUF;
        const uint32_t* Wc = Ws + p*WBUF;

        #pragma unroll
        for (int ks = 0; ks < 4; ks++) {
            uint32_t a[4][4];
            #pragma unroll
            for (int m = 0; m < 4; m++) {
                int row = m*16 + g;
                a[m][0] = f2tf32(Xc[row*XST + ks*8 + q]);
                a[m][1] = f2tf32(Xc[(row + 8)*XST + ks*8 + q]);
                a[m][2] = f2tf32(Xc[row*XST + ks*8 + q + 4]);
                a[m][3] = f2tf32(Xc[(row + 8)*XST + ks*8 + q + 4]);
            }
            #pragma unroll
            for (int j = 0; j < 6; j++) {
                int rn = w*48 + j*8 + g;
                uint32_t b0 = Wc[rn*WST + ks*8 + q];
                uint32_t b1 = Wc[rn*WST + ks*8 + q + 4];
                #pragma unroll
                for (int m = 0; m < 4; m++)
                    mma_tf32(acc[m][j], a[m], b0, b1);
            }
        }
        __syncthreads();
    }

    // epilogue: cols 0..63 -> g_k, 64..127 -> g_q, 128..191 -> g_vt (transposed)
    #pragma unroll
    for (int m = 0; m < 4; m++) {
        #pragma unroll
        for (int j = 0; j < 6; j++) {
            int gcol = w*48 + j*8 + q*2;
            int sel  = gcol >> 6;
            int col  = gcol & 63;
            int row  = row0 + m*16 + g;
            if (sel == 0) {
                *reinterpret_cast<float2*>(&g_k[(size_t)row*H_ + col]) =
                    make_float2(acc[m][j][0], acc[m][j][1]);
                *reinterpret_cast<float2*>(&g_k[(size_t)(row + 8)*H_ + col]) =
                    make_float2(acc[m][j][2], acc[m][j][3]);
            } else if (sel == 1) {
                *reinterpret_cast<float2*>(&g_q[(size_t)row*H_ + col]) =
                    make_float2(acc[m][j][0], acc[m][j][1]);
                *reinterpret_cast<float2*>(&g_q[(size_t)(row + 8)*H_ + col]) =
                    make_float2(acc[m][j][2], acc[m][j][3]);
            } else {
                int bb = row >> 12, t = row & 4095;
                float* vt = &g_vt[((size_t)bb*H_ + col)*T_ + t];
                vt[0]        = acc[m][j][0];
                vt[T_]       = acc[m][j][1];
                vt[8]        = acc[m][j][2];
                vt[T_ + 8]   = acc[m][j][3];
            }
        }
    }
}

// ---------------------------------------------------------------------------
// Kernel 2: flash attention partial pass (split-K), tf32 mma.
// ---------------------------------------------------------------------------
#define SS 68

__global__ __launch_bounds__(128) void attn_part_kernel()
{
    extern __shared__ uint32_t sm[];
    uint32_t* Ks  = sm;
    uint32_t* Vts = Ks + 64 * SS;
    uint32_t* Ps  = Vts + 64 * SS;

    const int qt = blockIdx.x;
    const int c  = blockIdx.y;
    const int b  = blockIdx.z;

    const int kb_lo = c * CHUNK_TILES;
    if (kb_lo > qt) return;
    const int kb_hi = min(qt, kb_lo + CHUNK_TILES - 1);

    const int tid = threadIdx.x;
    const int w   = tid >> 5;
    const int lane = tid & 31;
    const int g   = lane >> 2;
    const int q   = lane & 3;

    const float scale = 0.03125f;

    const float* qg = g_q + ((size_t)b * T_ + (size_t)qt * 64) * H_;
    for (int i = tid * 4; i < 64 * 64; i += 512) {
        int r = i >> 6, cc = i & 63;
        float4 v4 = *reinterpret_cast<const float4*>(&qg[r * 64 + cc]);
        uint4 u4 = make_uint4(f2tf32(v4.x * scale), f2tf32(v4.y * scale),
                              f2tf32(v4.z * scale), f2tf32(v4.w * scale));
        *reinterpret_cast<uint4*>(&Ps[r * SS + cc]) = u4;
    }
    __syncthreads();

    uint32_t qa[8][4];
    #pragma unroll
    for (int kk = 0; kk < 8; kk++) {
        int row = w * 16 + g;
        qa[kk][0] = Ps[row * SS + kk * 8 + q];
        qa[kk][1] = Ps[(row + 8) * SS + kk * 8 + q];
        qa[kk][2] = Ps[row * SS + kk * 8 + q + 4];
        qa[kk][3] = Ps[(row + 8) * SS + kk * 8 + q + 4];
    }

    float o[8][4] = {};
    float m0 = -1e30f, m1 = -1e30f, l0 = 0.0f, l1 = 0.0f;

    for (int kb = kb_lo; kb <= kb_hi; kb++) {
        const float* kg  = g_k  + ((size_t)b * T_ + (size_t)kb * 64) * H_;
        const float* vtg = g_vt + (size_t)b * H_ * T_ + (size_t)kb * 64;

        __syncthreads();
        // K tile: coalesced float4
        for (int i = tid * 4; i < 64 * 64; i += 512) {
            int r = i >> 6, cc = i & 63;
            float4 v4 = *reinterpret_cast<const float4*>(&kg[r * 64 + cc]);
            uint4 u4 = make_uint4(f2tf32(v4.x), f2tf32(v4.y), f2tf32(v4.z), f2tf32(v4.w));
            *reinterpret_cast<uint4*>(&Ks[r * SS + cc]) = u4;
        }
        // V^T tile from g_vt: coalesced LDG, conflict-free float4 STS
        #pragma unroll
        for (int it = 0; it < 8; it++) {
            int idx = tid + 128 * it;
            int h = idx >> 4, c4 = (idx & 15) * 4;
            float4 v4 = *reinterpret_cast<const float4*>(&vtg[(size_t)h * T_ + c4]);
            uint4 u4 = make_uint4(f2tf32(v4.x), f2tf32(v4.y), f2tf32(v4.z), f2tf32(v4.w));
            *reinterpret_cast<uint4*>(&Vts[h * SS + c4]) = u4;
        }
        __syncthreads();

        float s[8][4] = {};
        #pragma unroll
        for (int kk = 0; kk < 8; kk++) {
            #pragma unroll
            for (int n = 0; n < 8; n++) {
                uint32_t b0 = Ks[(n * 8 + g) * SS + kk * 8 + q];
                uint32_t b1 = Ks[(n * 8 + g) * SS + kk * 8 + q + 4];
                mma_tf32(s[n], qa[kk], b0, b1);
            }
        }

        if (kb == qt) {
            int r0 = w * 16 + g;
            #pragma unroll
            for (int n = 0; n < 8; n++) {
                int c0 = n * 8 + q * 2;
                if (c0     > r0)     s[n][0] = -1e30f;
                if (c0 + 1 > r0)     s[n][1] = -1e30f;
                if (c0     > r0 + 8) s[n][2] = -1e30f;
                if (c0 + 1 > r0 + 8) s[n][3] = -1e30f;
            }
        }

        float tmax0 = -1e30f, tmax1 = -1e30f;
        #pragma unroll
        for (int n = 0; n < 8; n++) {
            tmax0 = fmaxf(tmax0, fmaxf(s[n][0], s[n][1]));
            tmax1 = fmaxf(tmax1, fmaxf(s[n][2], s[n][3]));
        }
        tmax0 = fmaxf(tmax0, __shfl_xor_sync(0xffffffff, tmax0, 1));
        tmax0 = fmaxf(tmax0, __shfl_xor_sync(0xffffffff, tmax0, 2));
        tmax1 = fmaxf(tmax1, __shfl_xor_sync(0xffffffff, tmax1, 1));
        tmax1 = fmaxf(tmax1, __shfl_xor_sync(0xffffffff, tmax1, 2));

        float m0n = fmaxf(m0, tmax0);
        float m1n = fmaxf(m1, tmax1);
        float al0 = __expf(m0 - m0n);
        float al1 = __expf(m1 - m1n);

        float sum0 = 0.0f, sum1 = 0.0f;
        #pragma unroll
        for (int n = 0; n < 8; n++) {
            s[n][0] = __expf(s[n][0] - m0n);
            s[n][1] = __expf(s[n][1] - m0n);
            s[n][2] = __expf(s[n][2] - m1n);
            s[n][3] = __expf(s[n][3] - m1n);
            sum0 += s[n][0] + s[n][1];
            sum1 += s[n][2] + s[n][3];
        }
        sum0 += __shfl_xor_sync(0xffffffff, sum0, 1);
        sum0 += __shfl_xor_sync(0xffffffff, sum0, 2);
        sum1 += __shfl_xor_sync(0xffffffff, sum1, 1);
        sum1 += __shfl_xor_sync(0xffffffff, sum1, 2);

        l0 = l0 * al0 + sum0;  m0 = m0n;
        l1 = l1 * al1 + sum1;  m1 = m1n;

        #pragma unroll
        for (int n = 0; n < 8; n++) {
            o[n][0] *= al0; o[n][1] *= al0;
            o[n][2] *= al1; o[n][3] *= al1;
        }

        {
            int row = w * 16 + g;
            #pragma unroll
            for (int n = 0; n < 8; n++) {
                int col = n * 8 + q * 2;
                *reinterpret_cast<uint2*>(&Ps[row * SS + col]) =
                    make_uint2(f2tf32(s[n][0]), f2tf32(s[n][1]));
                *reinterpret_cast<uint2*>(&Ps[(row + 8) * SS + col]) =
                    make_uint2(f2tf32(s[n][2]), f2tf32(s[n][3]));
            }
        }
        __syncwarp();

        #pragma unroll
        for (int kk = 0; kk < 8; kk++) {
            int row = w * 16 + g;
            uint32_t pa[4];
            pa[0] = Ps[row * SS + kk * 8 + q];
            pa[1] = Ps[(row + 8) * SS + kk * 8 + q];
            pa[2] = Ps[row * SS + kk * 8 + q + 4];
            pa[3] = Ps[(row + 8) * SS + kk * 8 + q + 4];
            #pragma unroll
            for (int n = 0; n < 8; n++) {
                uint32_t b0 = Vts[(n * 8 + g) * SS + kk * 8 + q];
                uint32_t b1 = Vts[(n * 8 + g) * SS + kk * 8 + q + 4];
                mma_tf32(o[n], pa, b0, b1);
            }
        }
    }

    const size_t pbase = ((size_t)(b * NCHUNK + c) * 64 + qt);
    float* po = g_po + pbase * 64 * H_;
    float* pm = g_pm + pbase * 64;
    float* pl = g_pl + pbase * 64;

    const int r0 = w * 16 + g;
    #pragma unroll
    for (int n = 0; n < 8; n++) {
        int col = n * 8 + q * 2;
        *reinterpret_cast<float2*>(&po[r0 * H_ + col]) = make_float2(o[n][0], o[n][1]);
        *reinterpret_cast<float2*>(&po[(r0 + 8) * H_ + col]) = make_float2(o[n][2], o[n][3]);
    }
    if (q == 0) {
        pm[r0] = m0; pl[r0] = l0;
        pm[r0 + 8] = m1; pl[r0 + 8] = l1;
    }
}

// ---------------------------------------------------------------------------
// Kernel 3: merge split-K partials.
// ---------------------------------------------------------------------------
__global__ __launch_bounds__(256) void attn_merge_kernel(float* __restrict__ out)
{
    const int qt = blockIdx.x;
    const int b  = blockIdx.y;
    const int t  = threadIdx.x;
    const int row = t >> 2;
    const int c0  = (t & 3) * 16;

    const int nc = qt / CHUNK_TILES + 1;

    float m[NCHUNK], l[NCHUNK];
    float M = -1e30f;
    #pragma unroll
    for (int c = 0; c < NCHUNK; c++) {
        if (c < nc) {
            size_t pbase = ((size_t)(b * NCHUNK + c) * 64 + qt);
            m[c] = g_pm[pbase * 64 + row];
            l[c] = g_pl[pbase * 64 + row];
            M = fmaxf(M, m[c]);
        }
    }
    float L = 0.0f, sc[NCHUNK];
    #pragma unroll
    for (int c = 0; c < NCHUNK; c++) {
        if (c < nc) {
            sc[c] = __expf(m[c] - M);
            L += l[c] * sc[c];
        }
    }
    const float invL = 1.0f / L;

    float* og = out + ((size_t)b * T_ + (size_t)qt * 64 + row) * H_ + c0;

    #pragma unroll
    for (int j = 0; j < 16; j += 4) {
        float4 acc = make_float4(0.f, 0.f, 0.f, 0.f);
        #pragma unroll
        for (int c = 0; c < NCHUNK; c++) {
            if (c < nc) {
                size_t pbase = ((size_t)(b * NCHUNK + c) * 64 + qt);
                const float* po = g_po + (pbase * 64 + row) * H_ + c0 + j;
                float4 v4 = *reinterpret_cast<const float4*>(po);
                acc.x += v4.x * sc[c]; acc.y += v4.y * sc[c];
                acc.z += v4.z * sc[c]; acc.w += v4.w * sc[c];
            }
        }
        acc.x *= invL; acc.y *= invL; acc.z *= invL; acc.w *= invL;
        *reinterpret_cast<float4*>(&og[j]) = acc;
    }
}

// ---------------------------------------------------------------------------
extern "C" void kernel_launch(void* const* d_in, const int* in_sizes, int n_in,
                              void* d_out, int out_size)
{
    const float* x  = (const float*)d_in[0];
    const float* Wk = (const float*)d_in[1];
    const float* Wq = (const float*)d_in[2];
    const float* Wv = (const float*)d_in[3];
    float* out = (float*)d_out;

    wconv_kernel<<<768, 256>>>(Wk, Wq, Wv);

    const int qkv_smem = (2*XBUF + 2*WBUF) * (int)sizeof(float);
    cudaFuncSetAttribute(qkv_kernel,
                         cudaFuncAttributeMaxDynamicSharedMemorySize, qkv_smem);
    qkv_kernel<<<(B_*T_)/64, 128, qkv_smem>>>(x);

    const int attn_smem = 3 * 64 * SS * (int)sizeof(uint32_t);
    cudaFuncSetAttribute(attn_part_kernel,
                         cudaFuncAttributeMaxDynamicSharedMemorySize, attn_smem);
    attn_part_kernel<<<dim3(64, NCHUNK, B_), 128, attn_smem>>>();

    attn_merge_kernel<<<dim3(64, B_), 256>>>(out);
}

// round 5
// speedup vs baseline: 4.8475x; 1.0904x over previous
#include <cuda_runtime.h>
#include <cstdint>

#define B_ 4
#define T_ 4096
#define C_ 1024
#define H_ 64

#define NCHUNK 4
#define CHUNK_TILES 16

// Q: tf32 bits, pre-scaled, row-major [b][t][h]
__device__ uint32_t g_qf[B_*T_*H_];
// K, V^T: tf32 bits in mma-B-fragment swizzled layout, per 64-tile:
//   word = q*8+g + 32*nn + 256*hi + 512*kk   (4096 words / tile)
__device__ uint32_t g_kf[B_*64*4096];
__device__ uint32_t g_vf[B_*64*4096];
__device__ uint32_t g_wt[3*64*1024];      // [sel][n][k] tf32

__device__ float g_po[B_*NCHUNK*64*64*H_];
__device__ float g_pm[B_*NCHUNK*64*64];
__device__ float g_pl[B_*NCHUNK*64*64];

__device__ __forceinline__ uint32_t f2tf32(float x) {
    uint32_t r;
    asm("cvt.rna.tf32.f32 %0, %1;" : "=r"(r) : "f"(x));
    return r;
}

__device__ __forceinline__ void mma_tf32(float c[4], const uint32_t a[4],
                                         uint32_t b0, uint32_t b1) {
    asm volatile(
        "mma.sync.aligned.m16n8k8.row.col.f32.tf32.tf32.f32 "
        "{%0,%1,%2,%3}, {%4,%5,%6,%7}, {%8,%9}, {%0,%1,%2,%3};"
        : "+f"(c[0]), "+f"(c[1]), "+f"(c[2]), "+f"(c[3])
        : "r"(a[0]), "r"(a[1]), "r"(a[2]), "r"(a[3]), "r"(b0), "r"(b1));
}

__device__ __forceinline__ void cp16(uint32_t dst, const void* src) {
    asm volatile("cp.async.cg.shared.global [%0], [%1], 16;" :: "r"(dst), "l"(src));
}

// B-swizzled store: row j (n-dim of B), col d (k-dim of B)
__device__ __forceinline__ void store_bswz(uint32_t* base, int j, int d, float val) {
    int nn = j >> 3, gg = j & 7;
    int kk = d >> 3, hi = (d >> 2) & 1, qq = d & 3;
    base[(qq*8 + gg) + 32*nn + 256*hi + 512*kk] = f2tf32(val);
}

// ---------------------------------------------------------------------------
// Kernel 0: convert W -> tf32, transposed [n][k]
// ---------------------------------------------------------------------------
__global__ __launch_bounds__(256) void wconv_kernel(
    const float* __restrict__ Wk, const float* __restrict__ Wq,
    const float* __restrict__ Wv)
{
    int idx = blockIdx.x * 256 + threadIdx.x;
    int wi = idx >> 16;
    int r  = idx & 65535;
    int k  = r >> 6;
    int n  = r & 63;
    const float* W = (wi == 0) ? Wk : ((wi == 1) ? Wq : Wv);
    g_wt[((size_t)wi*64 + n)*1024 + k] = f2tf32(W[k*64 + n]);
}

// ---------------------------------------------------------------------------
// Kernel 1: fused QKV, cp.async double-buffered. Epilogue emits tf32 in
// attention-ready layouts (Q scaled row-major; K/V^T B-frag swizzled).
// ---------------------------------------------------------------------------
#define XST 36
#define WST 36
#define XBUF (64*XST)
#define WBUF (192*WST)

__global__ __launch_bounds__(128) void qkv_kernel(const float* __restrict__ x)
{
    extern __shared__ float smf[];
    float*    Xs = smf;
    uint32_t* Ws = (uint32_t*)(smf + 2*XBUF);

    const int row0 = blockIdx.x * 64;
    const int tid  = threadIdx.x;
    const int w    = tid >> 5;
    const int lane = tid & 31;
    const int g    = lane >> 2;
    const int q    = lane & 3;

    float acc[4][6][4] = {};

    {
        #pragma unroll
        for (int j = 0; j < 4; j++) {
            int idx = tid + 128*j;
            int r = idx >> 3, c4 = (idx & 7) * 4;
            cp16((uint32_t)__cvta_generic_to_shared(&Xs[r*XST + c4]),
                 &x[(size_t)(row0 + r)*C_ + c4]);
        }
        #pragma unroll
        for (int j = 0; j < 12; j++) {
            int idx = tid + 128*j;
            int r = idx >> 3, c4 = (idx & 7) * 4;
            cp16((uint32_t)__cvta_generic_to_shared(&Ws[r*WST + c4]),
                 &g_wt[(size_t)r*1024 + c4]);
        }
        asm volatile("cp.async.commit_group;");
    }

    for (int ch = 0; ch < 32; ch++) {
        const int p = ch & 1;
        if (ch + 1 < 32) {
            const int k0 = (ch + 1) * 32;
            const int pn = p ^ 1;
            #pragma unroll
            for (int j = 0; j < 4; j++) {
                int idx = tid + 128*j;
                int r = idx >> 3, c4 = (idx & 7) * 4;
                cp16((uint32_t)__cvta_generic_to_shared(&Xs[pn*XBUF + r*XST + c4]),
                     &x[(size_t)(row0 + r)*C_ + k0 + c4]);
            }
            #pragma unroll
            for (int j = 0; j < 12; j++) {
                int idx = tid + 128*j;
                int r = idx >> 3, c4 = (idx & 7) * 4;
                cp16((uint32_t)__cvta_generic_to_shared(&Ws[pn*WBUF + r*WST + c4]),
                     &g_wt[(size_t)r*1024 + k0 + c4]);
            }
            asm volatile("cp.async.commit_group;");
            asm volatile("cp.async.wait_group 1;");
        } else {
            asm volatile("cp.async.wait_group 0;");
        }
        __syncthreads();

        const float*    Xc = Xs + p*XBUF;
        const uint32_t* Wc = Ws + p*WBUF;

        #pragma unroll
        for (int ks = 0; ks < 4; ks++) {
            uint32_t a[4][4];
            #pragma unroll
            for (int m = 0; m < 4; m++) {
                int row = m*16 + g;
                a[m][0] = f2tf32(Xc[row*XST + ks*8 + q]);
                a[m][1] = f2tf32(Xc[(row + 8)*XST + ks*8 + q]);
                a[m][2] = f2tf32(Xc[row*XST + ks*8 + q + 4]);
                a[m][3] = f2tf32(Xc[(row + 8)*XST + ks*8 + q + 4]);
            }
            #pragma unroll
            for (int j = 0; j < 6; j++) {
                int rn = w*48 + j*8 + g;
                uint32_t b0 = Wc[rn*WST + ks*8 + q];
                uint32_t b1 = Wc[rn*WST + ks*8 + q + 4];
                #pragma unroll
                for (int m = 0; m < 4; m++)
                    mma_tf32(acc[m][j], a[m], b0, b1);
            }
        }
        __syncthreads();
    }

    // epilogue: sel 0 -> K (B-swz), 1 -> Q (scaled row-major), 2 -> V^T (B-swz)
    const float scale = 0.03125f;
    #pragma unroll
    for (int m = 0; m < 4; m++) {
        #pragma unroll
        for (int j = 0; j < 6; j++) {
            int gcol = w*48 + j*8 + q*2;
            int sel  = gcol >> 6;
            int col  = gcol & 63;
            int row  = row0 + m*16 + g;
            int bb = row >> 12, t = row & 4095;
            int kt = t >> 6, jj = t & 63;
            if (sel == 0) {
                uint32_t* base = g_kf + (((size_t)bb*64 + kt) << 12);
                store_bswz(base, jj,     col,     acc[m][j][0]);
                store_bswz(base, jj,     col + 1, acc[m][j][1]);
                store_bswz(base, jj + 8, col,     acc[m][j][2]);
                store_bswz(base, jj + 8, col + 1, acc[m][j][3]);
            } else if (sel == 1) {
                g_qf[(size_t)row*H_ + col]       = f2tf32(acc[m][j][0] * scale);
                g_qf[(size_t)row*H_ + col + 1]   = f2tf32(acc[m][j][1] * scale);
                g_qf[(size_t)(row+8)*H_ + col]   = f2tf32(acc[m][j][2] * scale);
                g_qf[(size_t)(row+8)*H_ + col+1] = f2tf32(acc[m][j][3] * scale);
            } else {
                // V: B-operand rows are h (col), cols are key index jj
                uint32_t* base = g_vf + (((size_t)bb*64 + kt) << 12);
                store_bswz(base, col,     jj,     acc[m][j][0]);
                store_bswz(base, col + 1, jj,     acc[m][j][1]);
                store_bswz(base, col,     jj + 8, acc[m][j][2]);
                store_bswz(base, col + 1, jj + 8, acc[m][j][3]);
            }
        }
    }
}

// ---------------------------------------------------------------------------
// Kernel 2: flash attention partial pass. cp.async double-buffered swizzled
// K/V tiles; conflict-free B-frag loads; zero cvt in the loop.
// ---------------------------------------------------------------------------
#define SS 68
#define TILE_W 4096   // words per K or V tile

__global__ __launch_bounds__(128) void attn_part_kernel()
{
    extern __shared__ uint32_t sm[];
    uint32_t* Kf = sm;                       // [2][4096]
    uint32_t* Vf = sm + 2*TILE_W;            // [2][4096]
    uint32_t* Ps = sm + 4*TILE_W;            // [64][SS]

    const int qt = blockIdx.x;
    const int c  = blockIdx.y;
    const int b  = blockIdx.z;

    const int kb_lo = c * CHUNK_TILES;
    if (kb_lo > qt) return;
    const int kb_hi = min(qt, kb_lo + CHUNK_TILES - 1);

    const int tid = threadIdx.x;
    const int w   = tid >> 5;
    const int lane = tid & 31;
    const int g   = lane >> 2;
    const int q   = lane & 3;
    const int bgq = q*8 + g;     // lane offset in B-swizzled tile

    // stage Q (already scaled tf32)
    const uint32_t* qg = g_qf + ((size_t)b * T_ + (size_t)qt * 64) * H_;
    for (int i = tid * 4; i < 64 * 64; i += 512) {
        int r = i >> 6, cc = i & 63;
        *reinterpret_cast<uint4*>(&Ps[r * SS + cc]) =
            *reinterpret_cast<const uint4*>(&qg[r * 64 + cc]);
    }

    const uint32_t* ktile = g_kf + (((size_t)b*64 + kb_lo) << 12);
    const uint32_t* vtile = g_vf + (((size_t)b*64 + kb_lo) << 12);

    // prologue prefetch
    #pragma unroll
    for (int j = 0; j < 8; j++) {
        int off = (tid + 128*j) * 4;
        cp16((uint32_t)__cvta_generic_to_shared(&Kf[off]), ktile + off);
        cp16((uint32_t)__cvta_generic_to_shared(&Vf[off]), vtile + off);
    }
    asm volatile("cp.async.commit_group;");

    __syncthreads();

    uint32_t qa[8][4];
    #pragma unroll
    for (int kk = 0; kk < 8; kk++) {
        int row = w * 16 + g;
        qa[kk][0] = Ps[row * SS + kk * 8 + q];
        qa[kk][1] = Ps[(row + 8) * SS + kk * 8 + q];
        qa[kk][2] = Ps[row * SS + kk * 8 + q + 4];
        qa[kk][3] = Ps[(row + 8) * SS + kk * 8 + q + 4];
    }

    float o[8][4] = {};
    float m0 = -1e30f, m1 = -1e30f, l0 = 0.0f, l1 = 0.0f;

    for (int kb = kb_lo; kb <= kb_hi; kb++) {
        const int p = (kb - kb_lo) & 1;
        if (kb < kb_hi) {
            const int pn = p ^ 1;
            const uint32_t* kt2 = g_kf + (((size_t)b*64 + kb + 1) << 12);
            const uint32_t* vt2 = g_vf + (((size_t)b*64 + kb + 1) << 12);
            #pragma unroll
            for (int j = 0; j < 8; j++) {
                int off = (tid + 128*j) * 4;
                cp16((uint32_t)__cvta_generic_to_shared(&Kf[pn*TILE_W + off]), kt2 + off);
                cp16((uint32_t)__cvta_generic_to_shared(&Vf[pn*TILE_W + off]), vt2 + off);
            }
            asm volatile("cp.async.commit_group;");
            asm volatile("cp.async.wait_group 1;");
        } else {
            asm volatile("cp.async.wait_group 0;");
        }
        __syncthreads();

        const uint32_t* Kc = Kf + p*TILE_W + bgq;
        const uint32_t* Vc = Vf + p*TILE_W + bgq;

        // S = Q @ K^T
        float s[8][4] = {};
        #pragma unroll
        for (int kk = 0; kk < 8; kk++) {
            #pragma unroll
            for (int n = 0; n < 8; n++) {
                uint32_t b0 = Kc[512*kk + 32*n];
                uint32_t b1 = Kc[512*kk + 32*n + 256];
                mma_tf32(s[n], qa[kk], b0, b1);
            }
        }

        if (kb == qt) {
            int r0 = w * 16 + g;
            #pragma unroll
            for (int n = 0; n < 8; n++) {
                int c0 = n * 8 + q * 2;
                if (c0     > r0)     s[n][0] = -1e30f;
                if (c0 + 1 > r0)     s[n][1] = -1e30f;
                if (c0     > r0 + 8) s[n][2] = -1e30f;
                if (c0 + 1 > r0 + 8) s[n][3] = -1e30f;
            }
        }

        float tmax0 = -1e30f, tmax1 = -1e30f;
        #pragma unroll
        for (int n = 0; n < 8; n++) {
            tmax0 = fmaxf(tmax0, fmaxf(s[n][0], s[n][1]));
            tmax1 = fmaxf(tmax1, fmaxf(s[n][2], s[n][3]));
        }
        tmax0 = fmaxf(tmax0, __shfl_xor_sync(0xffffffff, tmax0, 1));
        tmax0 = fmaxf(tmax0, __shfl_xor_sync(0xffffffff, tmax0, 2));
        tmax1 = fmaxf(tmax1, __shfl_xor_sync(0xffffffff, tmax1, 1));
        tmax1 = fmaxf(tmax1, __shfl_xor_sync(0xffffffff, tmax1, 2));

        float m0n = fmaxf(m0, tmax0);
        float m1n = fmaxf(m1, tmax1);
        float al0 = __expf(m0 - m0n);
        float al1 = __expf(m1 - m1n);

        float sum0 = 0.0f, sum1 = 0.0f;
        #pragma unroll
        for (int n = 0; n < 8; n++) {
            s[n][0] = __expf(s[n][0] - m0n);
            s[n][1] = __expf(s[n][1] - m0n);
            s[n][2] = __expf(s[n][2] - m1n);
            s[n][3] = __expf(s[n][3] - m1n);
            sum0 += s[n][0] + s[n][1];
            sum1 += s[n][2] + s[n][3];
        }
        sum0 += __shfl_xor_sync(0xffffffff, sum0, 1);
        sum0 += __shfl_xor_sync(0xffffffff, sum0, 2);
        sum1 += __shfl_xor_sync(0xffffffff, sum1, 1);
        sum1 += __shfl_xor_sync(0xffffffff, sum1, 2);

        l0 = l0 * al0 + sum0;  m0 = m0n;
        l1 = l1 * al1 + sum1;  m1 = m1n;

        #pragma unroll
        for (int n = 0; n < 8; n++) {
            o[n][0] *= al0; o[n][1] *= al0;
            o[n][2] *= al1; o[n][3] *= al1;
        }

        // P -> A-layout via per-warp smem roundtrip
        {
            int row = w * 16 + g;
            #pragma unroll
            for (int n = 0; n < 8; n++) {
                int col = n * 8 + q * 2;
                *reinterpret_cast<uint2*>(&Ps[row * SS + col]) =
                    make_uint2(f2tf32(s[n][0]), f2tf32(s[n][1]));
                *reinterpret_cast<uint2*>(&Ps[(row + 8) * SS + col]) =
                    make_uint2(f2tf32(s[n][2]), f2tf32(s[n][3]));
            }
        }
        __syncwarp();

        // O += P @ V
        #pragma unroll
        for (int kk = 0; kk < 8; kk++) {
            int row = w * 16 + g;
            uint32_t pa[4];
            pa[0] = Ps[row * SS + kk * 8 + q];
            pa[1] = Ps[(row + 8) * SS + kk * 8 + q];
            pa[2] = Ps[row * SS + kk * 8 + q + 4];
            pa[3] = Ps[(row + 8) * SS + kk * 8 + q + 4];
            #pragma unroll
            for (int n = 0; n < 8; n++) {
                uint32_t b0 = Vc[512*kk + 32*n];
                uint32_t b1 = Vc[512*kk + 32*n + 256];
                mma_tf32(o[n], pa, b0, b1);
            }
        }
        __syncthreads();   // stage buffers consumed; safe for next prefetch
    }

    const size_t pbase = ((size_t)(b * NCHUNK + c) * 64 + qt);
    float* po = g_po + pbase * 64 * H_;
    float* pm = g_pm + pbase * 64;
    float* pl = g_pl + pbase * 64;

    const int r0 = w * 16 + g;
    #pragma unroll
    for (int n = 0; n < 8; n++) {
        int col = n * 8 + q * 2;
        *reinterpret_cast<float2*>(&po[r0 * H_ + col]) = make_float2(o[n][0], o[n][1]);
        *reinterpret_cast<float2*>(&po[(r0 + 8) * H_ + col]) = make_float2(o[n][2], o[n][3]);
    }
    if (q == 0) {
        pm[r0] = m0; pl[r0] = l0;
        pm[r0 + 8] = m1; pl[r0 + 8] = l1;
    }
}

// ---------------------------------------------------------------------------
// Kernel 3: merge split-K partials.
// ---------------------------------------------------------------------------
__global__ __launch_bounds__(256) void attn_merge_kernel(float* __restrict__ out)
{
    const int qt = blockIdx.x;
    const int b  = blockIdx.y;
    const int t  = threadIdx.x;
    const int row = t >> 2;
    const int c0  = (t & 3) * 16;

    const int nc = qt / CHUNK_TILES + 1;

    float m[NCHUNK], l[NCHUNK];
    float M = -1e30f;
    #pragma unroll
    for (int c = 0; c < NCHUNK; c++) {
        if (c < nc) {
            size_t pbase = ((size_t)(b * NCHUNK + c) * 64 + qt);
            m[c] = g_pm[pbase * 64 + row];
            l[c] = g_pl[pbase * 64 + row];
            M = fmaxf(M, m[c]);
        }
    }
    float L = 0.0f, sc[NCHUNK];
    #pragma unroll
    for (int c = 0; c < NCHUNK; c++) {
        if (c < nc) {
            sc[c] = __expf(m[c] - M);
            L += l[c] * sc[c];
        }
    }
    const float invL = 1.0f / L;

    float* og = out + ((size_t)b * T_ + (size_t)qt * 64 + row) * H_ + c0;

    #pragma unroll
    for (int j = 0; j < 16; j += 4) {
        float4 acc = make_float4(0.f, 0.f, 0.f, 0.f);
        #pragma unroll
        for (int c = 0; c < NCHUNK; c++) {
            if (c < nc) {
                size_t pbase = ((size_t)(b * NCHUNK + c) * 64 + qt);
                const float* po = g_po + (pbase * 64 + row) * H_ + c0 + j;
                float4 v4 = *reinterpret_cast<const float4*>(po);
                acc.x += v4.x * sc[c]; acc.y += v4.y * sc[c];
                acc.z += v4.z * sc[c]; acc.w += v4.w * sc[c];
            }
        }
        acc.x *= invL; acc.y *= invL; acc.z *= invL; acc.w *= invL;
        *reinterpret_cast<float4*>(&og[j]) = acc;
    }
}

// ---------------------------------------------------------------------------
extern "C" void kernel_launch(void* const* d_in, const int* in_sizes, int n_in,
                              void* d_out, int out_size)
{
    const float* x  = (const float*)d_in[0];
    const float* Wk = (const float*)d_in[1];
    const float* Wq = (const float*)d_in[2];
    const float* Wv = (const float*)d_in[3];
    float* out = (float*)d_out;

    wconv_kernel<<<768, 256>>>(Wk, Wq, Wv);

    const int qkv_smem = (2*XBUF + 2*WBUF) * (int)sizeof(float);
    cudaFuncSetAttribute(qkv_kernel,
                         cudaFuncAttributeMaxDynamicSharedMemorySize, qkv_smem);
    qkv_kernel<<<(B_*T_)/64, 128, qkv_smem>>>(x);

    const int attn_smem = (4*TILE_W + 64*SS) * (int)sizeof(uint32_t);
    cudaFuncSetAttribute(attn_part_kernel,
                         cudaFuncAttributeMaxDynamicSharedMemorySize, attn_smem);
    attn_part_kernel<<<dim3(64, NCHUNK, B_), 128, attn_smem>>>();

    attn_merge_kernel<<<dim3(64, B_), 256>>>(out);
}